// round 12
// baseline (speedup 1.0000x reference)
#include <cuda_runtime.h>
#include <math.h>

#define D 128
#define HEADS 8
#define UNITS 16
#define N_NODES_MAX 50048
#define N_EDGES_MAX 800000
#define BUCKET 64            // max in-degree capacity (mean 16, P(>64) ~ e^-50)

// ---------------- device scratch (static globals: allocation-free) ----------
__device__ float g_xp[N_NODES_MAX * D];             // projected features (25.6 MB)
__device__ int   g_count[N_NODES_MAX];
__device__ int   g_csr_src[N_NODES_MAX * BUCKET];   // bucketed incoming-source lists
__device__ float g_Bhi[D * D];                      // tf32 hi part of weight
__device__ float g_Blo[D * D];                      // tf32 lo part of weight

// ---------------- tf32 helpers ---------------------------------------------
__device__ __forceinline__ unsigned f2tf32(float x) {
    unsigned r;
    asm("cvt.rna.tf32.f32 %0, %1;" : "=r"(r) : "f"(x));
    return r;
}

// prep: split weight into tf32 hi/lo AND zero the degree counters (one launch)
__global__ void prep_kernel(const float* __restrict__ B, int n) {
    int i = blockIdx.x * blockDim.x + threadIdx.x;
    if (i < D * D) {
        float v   = B[i];
        unsigned hi = f2tf32(v);
        float hif = __uint_as_float(hi);
        unsigned lo = f2tf32(v - hif);
        g_Bhi[i] = hif;
        g_Blo[i] = __uint_as_float(lo);
    }
    if (i < n) g_count[i] = 0;
}

#define MMA_TF32(c, a0, a1, a2, a3, b0, b1)                                   \
    asm volatile(                                                             \
        "mma.sync.aligned.m16n8k8.row.col.f32.tf32.tf32.f32 "                 \
        "{%0,%1,%2,%3}, {%4,%5,%6,%7}, {%8,%9}, {%0,%1,%2,%3};"               \
        : "+f"((c)[0]), "+f"((c)[1]), "+f"((c)[2]), "+f"((c)[3])              \
        : "r"(a0), "r"(a1), "r"(a2), "r"(a3), "r"(b0), "r"(b1))

// ---------------- fused GEMM + scatter ---------------------------------------
// Block roles interleaved 1:2 (gemm:scatter) so tensor-bound and L2-latency-
// bound blocks share every SM wave and the CSR build hides under the GEMM.
__global__ __launch_bounds__(256) void gemm_scatter_kernel(
    const float* __restrict__ A, const int2* __restrict__ edges,
    int M, int ne, int ng) {

    __shared__ float As[128 * 20];
    __shared__ float Bh[16 * 136];
    __shared__ float Bl[16 * 136];

    const int b   = blockIdx.x;
    const int tid = threadIdx.x;
    const bool is_gemm = ((b % 3) == 0) && (b / 3 < ng);

    if (!is_gemm) {
        // -------- scatter role: 1024 edges per block, 4 per thread ----------
        const int sb   = b - min((b + 2) / 3, ng);
        const int base = sb * 1024 + tid;
        int2 ed[4];
        bool vl[4];
#pragma unroll
        for (int j = 0; j < 4; j++) {
            int e = base + j * 256;
            vl[j] = (e < ne);
            ed[j] = vl[j] ? __ldg(&edges[e]) : make_int2(0, 0);
        }
#pragma unroll
        for (int j = 0; j < 4; j++) {
            if (vl[j]) {
                int pos = atomicAdd(&g_count[ed[j].y], 1);
                g_csr_src[ed[j].y * BUCKET + pos] = ed[j].x;
            }
        }
        return;
    }

    // ------------- gemm role: 128-row tile, tf32x3 ------------------------
    const int warp = tid >> 5;
    const int lane = tid & 31;
    const int row0 = (b / 3) * 128;
    const int lrow = lane >> 2;
    const int lcol = lane & 3;

    float c[16][4];
#pragma unroll
    for (int i = 0; i < 16; i++)
#pragma unroll
        for (int j = 0; j < 4; j++) c[i][j] = 0.0f;

    for (int s = 0; s < 8; s++) {
        const int kg = s * 16;
#pragma unroll
        for (int e = tid; e < 512; e += 256) {
            int r = e >> 2, c4 = (e & 3) << 2;
            float4 v = make_float4(0.f, 0.f, 0.f, 0.f);
            if (row0 + r < M) v = *(const float4*)&A[(row0 + r) * D + kg + c4];
            *(float4*)&As[r * 20 + c4] = v;
        }
#pragma unroll
        for (int e = tid; e < 512; e += 256) {
            int kk = e >> 5, c4 = (e & 31) << 2;
            *(float4*)&Bh[kk * 136 + c4] = *(const float4*)&g_Bhi[(kg + kk) * D + c4];
            *(float4*)&Bl[kk * 136 + c4] = *(const float4*)&g_Blo[(kg + kk) * D + c4];
        }
        __syncthreads();

#pragma unroll
        for (int ks = 0; ks < 2; ks++) {
            const int k0 = ks * 8;
            const int ar = warp * 16 + lrow;
            const int ac = k0 + lcol;
            float a0f = As[ar * 20 + ac];
            float a1f = As[(ar + 8) * 20 + ac];
            float a2f = As[ar * 20 + ac + 4];
            float a3f = As[(ar + 8) * 20 + ac + 4];
            unsigned ah0 = f2tf32(a0f), ah1 = f2tf32(a1f), ah2 = f2tf32(a2f), ah3 = f2tf32(a3f);
            unsigned al0 = f2tf32(a0f - __uint_as_float(ah0));
            unsigned al1 = f2tf32(a1f - __uint_as_float(ah1));
            unsigned al2 = f2tf32(a2f - __uint_as_float(ah2));
            unsigned al3 = f2tf32(a3f - __uint_as_float(ah3));

            const int bi0 = (k0 + lcol) * 136 + lrow;
            const int bi1 = (k0 + 4 + lcol) * 136 + lrow;
#pragma unroll
            for (int nt = 0; nt < 16; nt++) {
                int off = nt * 8;
                unsigned bh0 = __float_as_uint(Bh[bi0 + off]);
                unsigned bh1 = __float_as_uint(Bh[bi1 + off]);
                unsigned bl0 = __float_as_uint(Bl[bi0 + off]);
                unsigned bl1 = __float_as_uint(Bl[bi1 + off]);
                MMA_TF32(c[nt], ah0, ah1, ah2, ah3, bh0, bh1);
                MMA_TF32(c[nt], ah0, ah1, ah2, ah3, bl0, bl1);
                MMA_TF32(c[nt], al0, al1, al2, al3, bh0, bh1);
            }
        }
        __syncthreads();
    }

    const int er = row0 + warp * 16 + lrow;
    const int ec = lcol * 2;
#pragma unroll
    for (int nt = 0; nt < 16; nt++) {
        if (er < M)
            *(float2*)&g_xp[er * D + nt * 8 + ec] = make_float2(c[nt][0], c[nt][1]);
        if (er + 8 < M)
            *(float2*)&g_xp[(er + 8) * D + nt * 8 + ec] = make_float2(c[nt][2], c[nt][3]);
    }
}

// ---------------- fused GAT aggregation: warp per target node ---------------
__device__ __forceinline__ float gelu_tanh(float v) {
    float u = 0.7978845608028654f * (v + 0.044715f * v * v * v);
    return 0.5f * v * (1.0f + tanhf(u));
}

__global__ void aggregate_kernel(const float* __restrict__ katt1,
                                 const float* __restrict__ batt,
                                 const float* __restrict__ bias,
                                 float* __restrict__ out, int n_nodes) {
    const int gw   = (blockIdx.x * blockDim.x + threadIdx.x) >> 5;
    const int lane = threadIdx.x & 31;
    if (gw >= n_nodes) return;
    const int t = gw;
    const int f = lane * 4;

    const float4 a4  = *(const float4*)&katt1[f];
    const float4 ba4 = *(const float4*)&batt[f];
    const float4 xpt = *(const float4*)&g_xp[t * D + f];
    float4 xbt;
    xbt.x = xpt.x + 2.0f * ba4.x;
    xbt.y = xpt.y + 2.0f * ba4.y;
    xbt.z = xpt.z + 2.0f * ba4.z;
    xbt.w = xpt.w + 2.0f * ba4.w;

    const int cnt  = g_count[t];
    const int base = t * BUCKET;

    float  m    = __int_as_float(0xff800000);
    float  ssum = 0.0f;
    float4 acc  = make_float4(0.f, 0.f, 0.f, 0.f);

    // depth-2 pipeline: index prefetched 2 ahead, features 1 ahead
    int sA = (cnt > 0) ? __ldg(&g_csr_src[base])     : 0;   // src of edge 1 (next)
    int sB = (cnt > 1) ? __ldg(&g_csr_src[base + 1]) : 0;   // src of edge 2
    float4 xs_nxt = make_float4(0.f, 0.f, 0.f, 0.f);
    if (cnt > 0) xs_nxt = *(const float4*)&g_xp[sA * D + f];

    for (int i = 0; i < cnt; i++) {
        float4 xs = xs_nxt;
        sA = sB;
        if (i + 2 < cnt) sB = __ldg(&g_csr_src[base + i + 2]);
        if (i + 1 < cnt) xs_nxt = *(const float4*)&g_xp[sA * D + f];

        float ex = xbt.x + xs.x;  ex = fmaxf(ex, 0.2f * ex);
        float ey = xbt.y + xs.y;  ey = fmaxf(ey, 0.2f * ey);
        float ez = xbt.z + xs.z;  ez = fmaxf(ez, 0.2f * ez);
        float ew = xbt.w + xs.w;  ew = fmaxf(ew, 0.2f * ew);

        float p = ex * a4.x + ey * a4.y + ez * a4.z + ew * a4.w;
        p += __shfl_xor_sync(0xffffffffu, p, 1);
        p += __shfl_xor_sync(0xffffffffu, p, 2);

        float nm    = fmaxf(m, p);
        float scale = __expf(m - nm);
        float w     = __expf(p - nm);
        ssum = ssum * scale + w;
        acc.x = acc.x * scale + w * xs.x;
        acc.y = acc.y * scale + w * xs.y;
        acc.z = acc.z * scale + w * xs.z;
        acc.w = acc.w * scale + w * xs.w;
        m = nm;
    }

    const float inv = 1.0f / (ssum + 1e-7f);
    const float4 b4 = *(const float4*)&bias[f];
    float4 o;
    o.x = gelu_tanh(acc.x * inv + b4.x);
    o.y = gelu_tanh(acc.y * inv + b4.y);
    o.z = gelu_tanh(acc.z * inv + b4.z);
    o.w = gelu_tanh(acc.w * inv + b4.w);
    *(float4*)&out[t * D + f] = o;
}

// ---------------- launch ----------------------------------------------------
extern "C" void kernel_launch(void* const* d_in, const int* in_sizes, int n_in,
                              void* d_out, int out_size) {
    const float* x     = (const float*)d_in[0];
    const int2*  edges = (const int2*) d_in[1];
    const float* kern  = (const float*)d_in[2];
    const float* katt1 = (const float*)d_in[3];
    const float* batt  = (const float*)d_in[4];
    const float* bias  = (const float*)d_in[5];
    float* out = (float*)d_out;

    const int n_nodes = in_sizes[0] / D;
    const int n_edges = in_sizes[1] / 2;
    const int ng = (n_nodes + 127) / 128;           // gemm blocks
    const int ns = (n_edges + 1023) / 1024;         // scatter blocks
    const int prep_n = (n_nodes > D * D) ? n_nodes : D * D;

    // 1) weight split + counter zero (one small launch)
    prep_kernel<<<(prep_n + 255) / 256, 256>>>(kern, n_nodes);

    // 2) fused: projection GEMM (tensor) + CSR scatter (L2), overlapped
    gemm_scatter_kernel<<<ng + ns, 256>>>(x, edges, n_nodes, n_edges, ng);

    // 3) fused attention + online softmax + aggregation + bias + GELU
    aggregate_kernel<<<(n_nodes * 32 + 255) / 256, 256>>>(katt1, batt, bias, out, n_nodes);
}

// round 17
// speedup vs baseline: 1.0129x; 1.0129x over previous
#include <cuda_runtime.h>
#include <math.h>

#define D 128
#define HEADS 8
#define UNITS 16
#define N_NODES_MAX 50048
#define N_EDGES_MAX 800000
#define BUCKET 64            // max in-degree capacity (mean 16, P(>64) ~ e^-50)

// ---------------- device scratch (static globals: allocation-free) ----------
__device__ float g_xp[N_NODES_MAX * D];             // projected features (25.6 MB)
__device__ int   g_count[N_NODES_MAX];
__device__ int   g_csr_src[N_NODES_MAX * BUCKET];   // bucketed incoming-source lists
__device__ float g_Bhi[D * D];                      // tf32 hi part of weight
__device__ float g_Blo[D * D];                      // tf32 lo part of weight

// ---------------- tf32 helpers ---------------------------------------------
__device__ __forceinline__ unsigned f2tf32(float x) {
    unsigned r;
    asm("cvt.rna.tf32.f32 %0, %1;" : "=r"(r) : "f"(x));
    return r;
}

// prep: split weight into tf32 hi/lo AND zero the degree counters (one launch)
__global__ void prep_kernel(const float* __restrict__ B, int n) {
    int i = blockIdx.x * blockDim.x + threadIdx.x;
    if (i < D * D) {
        float v   = B[i];
        unsigned hi = f2tf32(v);
        float hif = __uint_as_float(hi);
        unsigned lo = f2tf32(v - hif);
        g_Bhi[i] = hif;
        g_Blo[i] = __uint_as_float(lo);
    }
    if (i < n) g_count[i] = 0;
}

#define MMA_TF32(c, a0, a1, a2, a3, b0, b1)                                   \
    asm volatile(                                                             \
        "mma.sync.aligned.m16n8k8.row.col.f32.tf32.tf32.f32 "                 \
        "{%0,%1,%2,%3}, {%4,%5,%6,%7}, {%8,%9}, {%0,%1,%2,%3};"               \
        : "+f"((c)[0]), "+f"((c)[1]), "+f"((c)[2]), "+f"((c)[3])              \
        : "r"(a0), "r"(a1), "r"(a2), "r"(a3), "r"(b0), "r"(b1))

// ---------------- GEMM: xp = x @ W via tf32 tensor cores (tf32x3) ----------
__global__ __launch_bounds__(256) void gemm_tf32_kernel(const float* __restrict__ A, int M) {
    __shared__ float As[128 * 20];
    __shared__ float Bh[16 * 136];
    __shared__ float Bl[16 * 136];

    const int tid  = threadIdx.x;
    const int warp = tid >> 5;
    const int lane = tid & 31;
    const int row0 = blockIdx.x * 128;
    const int lrow = lane >> 2;
    const int lcol = lane & 3;

    float c[16][4];
#pragma unroll
    for (int i = 0; i < 16; i++)
#pragma unroll
        for (int j = 0; j < 4; j++) c[i][j] = 0.0f;

    for (int s = 0; s < 8; s++) {
        const int kg = s * 16;
#pragma unroll
        for (int e = tid; e < 512; e += 256) {
            int r = e >> 2, c4 = (e & 3) << 2;
            float4 v = make_float4(0.f, 0.f, 0.f, 0.f);
            if (row0 + r < M) v = *(const float4*)&A[(row0 + r) * D + kg + c4];
            *(float4*)&As[r * 20 + c4] = v;
        }
#pragma unroll
        for (int e = tid; e < 512; e += 256) {
            int kk = e >> 5, c4 = (e & 31) << 2;
            *(float4*)&Bh[kk * 136 + c4] = *(const float4*)&g_Bhi[(kg + kk) * D + c4];
            *(float4*)&Bl[kk * 136 + c4] = *(const float4*)&g_Blo[(kg + kk) * D + c4];
        }
        __syncthreads();

#pragma unroll
        for (int ks = 0; ks < 2; ks++) {
            const int k0 = ks * 8;
            const int ar = warp * 16 + lrow;
            const int ac = k0 + lcol;
            float a0f = As[ar * 20 + ac];
            float a1f = As[(ar + 8) * 20 + ac];
            float a2f = As[ar * 20 + ac + 4];
            float a3f = As[(ar + 8) * 20 + ac + 4];
            unsigned ah0 = f2tf32(a0f), ah1 = f2tf32(a1f), ah2 = f2tf32(a2f), ah3 = f2tf32(a3f);
            unsigned al0 = f2tf32(a0f - __uint_as_float(ah0));
            unsigned al1 = f2tf32(a1f - __uint_as_float(ah1));
            unsigned al2 = f2tf32(a2f - __uint_as_float(ah2));
            unsigned al3 = f2tf32(a3f - __uint_as_float(ah3));

            const int bi0 = (k0 + lcol) * 136 + lrow;
            const int bi1 = (k0 + 4 + lcol) * 136 + lrow;
#pragma unroll
            for (int nt = 0; nt < 16; nt++) {
                int off = nt * 8;
                unsigned bh0 = __float_as_uint(Bh[bi0 + off]);
                unsigned bh1 = __float_as_uint(Bh[bi1 + off]);
                unsigned bl0 = __float_as_uint(Bl[bi0 + off]);
                unsigned bl1 = __float_as_uint(Bl[bi1 + off]);
                MMA_TF32(c[nt], ah0, ah1, ah2, ah3, bh0, bh1);
                MMA_TF32(c[nt], ah0, ah1, ah2, ah3, bl0, bl1);
                MMA_TF32(c[nt], al0, al1, al2, al3, bh0, bh1);
            }
        }
        __syncthreads();
    }

    const int er = row0 + warp * 16 + lrow;
    const int ec = lcol * 2;
#pragma unroll
    for (int nt = 0; nt < 16; nt++) {
        if (er < M)
            *(float2*)&g_xp[er * D + nt * 8 + ec] = make_float2(c[nt][0], c[nt][1]);
        if (er + 8 < M)
            *(float2*)&g_xp[(er + 8) * D + nt * 8 + ec] = make_float2(c[nt][2], c[nt][3]);
    }
}

// ---------------- bucketed CSR scatter: 4 edges/thread, int4 loads ----------
__global__ void scatter_kernel(const int4* __restrict__ edges4, int ne) {
    const int t4 = blockIdx.x * blockDim.x + threadIdx.x;  // handles edges [4t, 4t+4)
    const int e0 = t4 * 4;
    if (e0 >= ne) return;

    if (e0 + 3 < ne) {
        int4 a = __ldg(&edges4[t4 * 2]);        // edges e0, e0+1
        int4 b = __ldg(&edges4[t4 * 2 + 1]);    // edges e0+2, e0+3
        int p0 = atomicAdd(&g_count[a.y], 1);
        int p1 = atomicAdd(&g_count[a.w], 1);
        int p2 = atomicAdd(&g_count[b.y], 1);
        int p3 = atomicAdd(&g_count[b.w], 1);
        g_csr_src[a.y * BUCKET + p0] = a.x;
        g_csr_src[a.w * BUCKET + p1] = a.z;
        g_csr_src[b.y * BUCKET + p2] = b.x;
        g_csr_src[b.w * BUCKET + p3] = b.z;
    } else {
        const int2* e2 = (const int2*)edges4;
        for (int e = e0; e < ne; e++) {
            int2 ed = __ldg(&e2[e]);
            int pos = atomicAdd(&g_count[ed.y], 1);
            g_csr_src[ed.y * BUCKET + pos] = ed.x;
        }
    }
}

// ---------------- fused GAT aggregation: warp per target node ---------------
__device__ __forceinline__ float gelu_tanh(float v) {
    float u = 0.7978845608028654f * (v + 0.044715f * v * v * v);
    return 0.5f * v * (1.0f + tanhf(u));
}

__global__ __launch_bounds__(256) void aggregate_kernel(
        const float* __restrict__ katt1,
        const float* __restrict__ batt,
        const float* __restrict__ bias,
        float* __restrict__ out, int n_nodes) {
    const int gw   = (blockIdx.x * blockDim.x + threadIdx.x) >> 5;
    const int lane = threadIdx.x & 31;
    if (gw >= n_nodes) return;
    const int t = gw;
    const int f = lane * 4;

    const float4 a4  = *(const float4*)&katt1[f];
    const float4 ba4 = *(const float4*)&batt[f];
    const float4 xpt = *(const float4*)&g_xp[t * D + f];
    float4 xbt;
    xbt.x = xpt.x + 2.0f * ba4.x;
    xbt.y = xpt.y + 2.0f * ba4.y;
    xbt.z = xpt.z + 2.0f * ba4.z;
    xbt.w = xpt.w + 2.0f * ba4.w;

    const int cnt  = g_count[t];
    const int base = t * BUCKET;
    const float4 b4 = *(const float4*)&bias[f];

    float  m    = __int_as_float(0xff800000);
    float  ssum = 0.0f;
    float4 acc  = make_float4(0.f, 0.f, 0.f, 0.f);

    if (cnt > 0) {
        // branch-free depth-2 pipeline: indices clamped so every load is valid.
        const int last = cnt - 1;
        int s0 = __ldg(&g_csr_src[base]);                       // edge 0
        int s1 = __ldg(&g_csr_src[base + min(1, last)]);        // edge 1
        float4 x0 = *(const float4*)&g_xp[s0 * D + f];
        float4 x1 = *(const float4*)&g_xp[s1 * D + f];
        int s2 = __ldg(&g_csr_src[base + min(2, last)]);        // edge 2

        for (int i = 0; i < cnt; i++) {
            float4 xs = x0;
            x0 = x1;
            x1 = *(const float4*)&g_xp[s2 * D + f];             // feature for edge i+2
            s2 = __ldg(&g_csr_src[base + min(i + 3, last)]);    // index for edge i+3

            float ex = xbt.x + xs.x;  ex = fmaxf(ex, 0.2f * ex);
            float ey = xbt.y + xs.y;  ey = fmaxf(ey, 0.2f * ey);
            float ez = xbt.z + xs.z;  ez = fmaxf(ez, 0.2f * ez);
            float ew = xbt.w + xs.w;  ew = fmaxf(ew, 0.2f * ew);

            float p = ex * a4.x + ey * a4.y + ez * a4.z + ew * a4.w;
            p += __shfl_xor_sync(0xffffffffu, p, 1);
            p += __shfl_xor_sync(0xffffffffu, p, 2);

            float nm    = fmaxf(m, p);
            float scale = __expf(m - nm);
            float w     = __expf(p - nm);
            ssum = ssum * scale + w;
            acc.x = acc.x * scale + w * xs.x;
            acc.y = acc.y * scale + w * xs.y;
            acc.z = acc.z * scale + w * xs.z;
            acc.w = acc.w * scale + w * xs.w;
            m = nm;
        }
    }

    const float inv = 1.0f / (ssum + 1e-7f);
    float4 o;
    o.x = gelu_tanh(acc.x * inv + b4.x);
    o.y = gelu_tanh(acc.y * inv + b4.y);
    o.z = gelu_tanh(acc.z * inv + b4.z);
    o.w = gelu_tanh(acc.w * inv + b4.w);
    *(float4*)&out[t * D + f] = o;
}

// ---------------- launch ----------------------------------------------------
extern "C" void kernel_launch(void* const* d_in, const int* in_sizes, int n_in,
                              void* d_out, int out_size) {
    const float* x     = (const float*)d_in[0];
    const float* kern  = (const float*)d_in[2];
    const float* katt1 = (const float*)d_in[3];
    const float* batt  = (const float*)d_in[4];
    const float* bias  = (const float*)d_in[5];
    float* out = (float*)d_out;

    const int n_nodes = in_sizes[0] / D;
    const int n_edges = in_sizes[1] / 2;
    const int prep_n  = (n_nodes > D * D) ? n_nodes : D * D;

    // 1) weight split + counter zero (one small launch)
    prep_kernel<<<(prep_n + 255) / 256, 256>>>(kern, n_nodes);

    // 2) projection GEMM on tensor cores (tf32x3)
    gemm_tf32_kernel<<<(n_nodes + 127) / 128, 256>>>(x, n_nodes);

    // 3) bucketed CSR scatter (4 edges/thread, vectorized loads)
    const int nthreads = (n_edges + 3) / 4;
    scatter_kernel<<<(nthreads + 255) / 256, 256>>>((const int4*)d_in[1], n_edges);

    // 4) fused attention + online softmax + aggregation + bias + GELU
    aggregate_kernel<<<(n_nodes * 32 + 255) / 256, 256>>>(katt1, batt, bias, out, n_nodes);
}